// round 1
// baseline (speedup 1.0000x reference)
#include <cuda_runtime.h>
#include <cuda_bf16.h>
#include <math.h>

// ---------------------------------------------------------------------------
// MambaDecoder: B=1, L=1024, D=1024, NL=4, DI=2048, N=16, DTR=64, K=4
// All fp32. Residual stream kept in d_out.
// ---------------------------------------------------------------------------

#define LSEQ 1024
#define DMODEL 1024
#define DI 2048
#define NSTATE 16
#define DTR 64
#define NL 4

// Scratch (no allocations allowed)
__device__ float g_xn[LSEQ * DMODEL];      // 4 MB
__device__ float g_xz[LSEQ * 2 * DI];      // 16 MB
__device__ float g_uc[LSEQ * DI];          // 8 MB
__device__ float g_xdbl[LSEQ * 96];        // 0.4 MB
__device__ float g_delta[LSEQ * DI];       // 8 MB
__device__ float g_yg[LSEQ * DI];          // 8 MB
__device__ float g_A[DI * NSTATE];         // 128 KB
__device__ int   g_flag;

// ---------------------------------------------------------------- rmsnorm --
__global__ void rmsnorm_kernel(const float* __restrict__ x,
                               const float* __restrict__ w,
                               float* __restrict__ out)
{
    int l = blockIdx.x;
    int t = threadIdx.x;            // 256 threads, 4 floats each
    const float4* xr = (const float4*)(x + l * DMODEL);
    float4 v = xr[t];
    float ss = v.x*v.x + v.y*v.y + v.z*v.z + v.w*v.w;
#pragma unroll
    for (int o = 16; o > 0; o >>= 1) ss += __shfl_xor_sync(0xffffffffu, ss, o);
    __shared__ float sred[8];
    if ((t & 31) == 0) sred[t >> 5] = ss;
    __syncthreads();
    float tot = 0.f;
#pragma unroll
    for (int i = 0; i < 8; i++) tot += sred[i];
    float rs = rsqrtf(tot * (1.0f / DMODEL) + 1e-5f);
    float4 wv = ((const float4*)w)[t];
    float4 o4 = make_float4(v.x*rs*wv.x, v.y*rs*wv.y, v.z*rs*wv.z, v.w*rs*wv.w);
    ((float4*)(out + l * DMODEL))[t] = o4;
}

// ------------------------------------------------------------------ sgemm --
// C[M,N] (+)= A[M,K] * B[N,K]^T   (both A,B row-major with K contiguous)
// BM=BN=128, BK=8, 256 threads, 8x8 per thread. All dims multiples of tile.
template<bool ACC>
__global__ void __launch_bounds__(256) sgemm128(
    const float* __restrict__ A, const float* __restrict__ B,
    float* __restrict__ C, int M, int N, int K)
{
    __shared__ float As[8][128];
    __shared__ float Bs[8][128];
    const int tid = threadIdx.x;
    const int bm = blockIdx.y * 128;
    const int bn = blockIdx.x * 128;
    const int lr = tid >> 1;
    const int lc = (tid & 1) << 2;
    const float* Ap = A + (size_t)(bm + lr) * K + lc;
    const float* Bp = B + (size_t)(bn + lr) * K + lc;
    const int tx = tid & 15;
    const int ty = tid >> 4;

    float acc[8][8];
#pragma unroll
    for (int i = 0; i < 8; i++)
#pragma unroll
        for (int j = 0; j < 8; j++) acc[i][j] = 0.f;

    float4 av = *(const float4*)Ap;
    float4 bv = *(const float4*)Bp;

    for (int k0 = 0; k0 < K; k0 += 8) {
        __syncthreads();
        As[lc+0][lr] = av.x; As[lc+1][lr] = av.y; As[lc+2][lr] = av.z; As[lc+3][lr] = av.w;
        Bs[lc+0][lr] = bv.x; Bs[lc+1][lr] = bv.y; Bs[lc+2][lr] = bv.z; Bs[lc+3][lr] = bv.w;
        __syncthreads();
        if (k0 + 8 < K) {
            av = *(const float4*)(Ap + k0 + 8);
            bv = *(const float4*)(Bp + k0 + 8);
        }
#pragma unroll
        for (int kk = 0; kk < 8; kk++) {
            float a[8], b[8];
            *(float4*)&a[0] = *(const float4*)&As[kk][ty * 4];
            *(float4*)&a[4] = *(const float4*)&As[kk][64 + ty * 4];
            *(float4*)&b[0] = *(const float4*)&Bs[kk][tx * 4];
            *(float4*)&b[4] = *(const float4*)&Bs[kk][64 + tx * 4];
#pragma unroll
            for (int i = 0; i < 8; i++)
#pragma unroll
                for (int j = 0; j < 8; j++)
                    acc[i][j] = fmaf(a[i], b[j], acc[i][j]);
        }
    }

#pragma unroll
    for (int ih = 0; ih < 2; ih++)
#pragma unroll
        for (int i = 0; i < 4; i++) {
            int row = bm + ih * 64 + ty * 4 + i;
#pragma unroll
            for (int jh = 0; jh < 2; jh++) {
                float* cp = C + (size_t)row * N + bn + jh * 64 + tx * 4;
                float4 r;
                if (ACC) {
                    float4 o = *(float4*)cp;
                    r = make_float4(o.x + acc[ih*4+i][jh*4+0],
                                    o.y + acc[ih*4+i][jh*4+1],
                                    o.z + acc[ih*4+i][jh*4+2],
                                    o.w + acc[ih*4+i][jh*4+3]);
                } else {
                    r = make_float4(acc[ih*4+i][jh*4+0], acc[ih*4+i][jh*4+1],
                                    acc[ih*4+i][jh*4+2], acc[ih*4+i][jh*4+3]);
                }
                *(float4*)cp = r;
            }
        }
}

// ------------------------------------------------------------- conv+silu --
__global__ void conv_silu_kernel(const float* __restrict__ xz,
                                 const float* __restrict__ w,
                                 const float* __restrict__ b,
                                 float* __restrict__ uc)
{
    int idx = blockIdx.x * 256 + threadIdx.x;   // over L*DI
    int l = idx >> 11;
    int d = idx & (DI - 1);
    float s = b[d];
#pragma unroll
    for (int k = 0; k < 4; k++) {
        int tl = l + k - 3;
        if (tl >= 0) s += xz[(size_t)tl * (2*DI) + d] * __ldg(&w[d * 4 + k]);
    }
    uc[idx] = s / (1.f + __expf(-s));
}

// ------------------------------------------------------------------ xproj --
// xdbl[L,96] = uc[L,2048] @ W[96,2048]^T   ; 32 l-rows per block, 256 thr
__global__ void __launch_bounds__(256) xproj_kernel(
    const float* __restrict__ uc, const float* __restrict__ W,
    float* __restrict__ xdbl)
{
    __shared__ float sW[96][65];
    __shared__ float sU[32][64];
    const int tid = threadIdx.x;
    const int l0 = blockIdx.x * 32;
    const int tx = tid & 31;
    const int ty = tid >> 5;     // 0..7
    float acc[4][3];
#pragma unroll
    for (int i = 0; i < 4; i++)
#pragma unroll
        for (int j = 0; j < 3; j++) acc[i][j] = 0.f;

    for (int k0 = 0; k0 < DI; k0 += 64) {
        __syncthreads();
#pragma unroll
        for (int i = 0; i < 24; i++) {
            int v = tid + i * 256;          // 0..6143
            int ee = v >> 6, rr = v & 63;
            sW[ee][rr] = W[(size_t)ee * DI + k0 + rr];
        }
#pragma unroll
        for (int i = 0; i < 8; i++) {
            int v = tid + i * 256;          // 0..2047
            int ll = v >> 6, rr = v & 63;
            sU[ll][rr] = uc[(size_t)(l0 + ll) * DI + k0 + rr];
        }
        __syncthreads();
#pragma unroll
        for (int r = 0; r < 64; r++) {
            float uv[4], wv[3];
#pragma unroll
            for (int i = 0; i < 4; i++) uv[i] = sU[ty * 4 + i][r];
#pragma unroll
            for (int j = 0; j < 3; j++) wv[j] = sW[j * 32 + tx][r];
#pragma unroll
            for (int i = 0; i < 4; i++)
#pragma unroll
                for (int j = 0; j < 3; j++)
                    acc[i][j] = fmaf(uv[i], wv[j], acc[i][j]);
        }
    }
#pragma unroll
    for (int i = 0; i < 4; i++)
#pragma unroll
        for (int j = 0; j < 3; j++)
            xdbl[(size_t)(l0 + ty * 4 + i) * 96 + j * 32 + tx] = acc[i][j];
}

// --------------------------------------------------------------------- dt --
// delta[L,DI] = softplus(xdbl[:, :64] @ dtw[DI,64]^T + dtb)
__global__ void __launch_bounds__(256) dt_kernel(
    const float* __restrict__ xdbl, const float* __restrict__ dtw,
    const float* __restrict__ dtb, float* __restrict__ delta)
{
    __shared__ float sW[128][65];
    __shared__ float sR[32][64];
    const int tid = threadIdx.x;
    const int d0 = blockIdx.x * 128;
    const int l0 = blockIdx.y * 32;
#pragma unroll
    for (int i = 0; i < 32; i++) {
        int v = tid + i * 256;               // 0..8191
        int dd = v >> 6, rr = v & 63;
        sW[dd][rr] = dtw[(size_t)(d0 + dd) * 64 + rr];
    }
#pragma unroll
    for (int i = 0; i < 8; i++) {
        int v = tid + i * 256;               // 0..2047
        int ll = v >> 6, rr = v & 63;
        sR[ll][rr] = xdbl[(size_t)(l0 + ll) * 96 + rr];
    }
    __syncthreads();
    const int tx = tid & 31;
    const int ty = tid >> 5;                 // 0..7
    float acc[4][4];
#pragma unroll
    for (int i = 0; i < 4; i++)
#pragma unroll
        for (int j = 0; j < 4; j++) acc[i][j] = 0.f;
#pragma unroll
    for (int r = 0; r < 64; r++) {
        float rv[4], wv[4];
#pragma unroll
        for (int i = 0; i < 4; i++) rv[i] = sR[ty * 4 + i][r];
#pragma unroll
        for (int j = 0; j < 4; j++) wv[j] = sW[j * 32 + tx][r];
#pragma unroll
        for (int i = 0; i < 4; i++)
#pragma unroll
            for (int j = 0; j < 4; j++)
                acc[i][j] = fmaf(rv[i], wv[j], acc[i][j]);
    }
#pragma unroll
    for (int i = 0; i < 4; i++)
#pragma unroll
        for (int j = 0; j < 4; j++) {
            int d = d0 + j * 32 + tx;
            float xv = acc[i][j] + __ldg(&dtb[d]);
            // stable softplus: max(x,0)+log1p(exp(-|x|))
            float sp = fmaxf(xv, 0.f) + log1pf(__expf(-fabsf(xv)));
            delta[(size_t)(l0 + ty * 4 + i) * DI + d] = sp;
        }
}

// ------------------------------------------------------------------ A prep --
__global__ void set_flag_kernel() { g_flag = 1; }

__global__ void prepA_kernel(const float* __restrict__ Alog)
{
    int i = blockIdx.x * 256 + threadIdx.x;   // < DI*NSTATE
    float a = -expf(Alog[i]);
    g_A[i] = a;
    int n = i & 15;
    if (fabsf(a + (float)(n + 1)) > 1e-5f * (float)(n + 1)) g_flag = 0;
}

// ------------------------------------------------------------------- scan --
// One thread per channel d. h[n] = exp(delta*A_n)*h + delta*u*B_n; y=<h,C>.
// Fast path (A_n == -(n+1)): dA_n = r^(n+1), r = exp(-delta), log-depth ladder.
__global__ void __launch_bounds__(32) scan_kernel(
    const float* __restrict__ delta, const float* __restrict__ xdbl,
    const float* __restrict__ uc, const float* __restrict__ xz,
    const float* __restrict__ Amat, const float* __restrict__ Dsk,
    float* __restrict__ yg)
{
    const int d = blockIdx.x * 32 + threadIdx.x;
    __shared__ float sBC[64][32];             // [t][0:16)=B, [16:32)=C
    float a[NSTATE], h[NSTATE];
#pragma unroll
    for (int n = 0; n < NSTATE; n++) { a[n] = Amat[d * NSTATE + n]; h[n] = 0.f; }
    const float dsk = Dsk[d];
    const int fast = g_flag;

    for (int t0 = 0; t0 < LSEQ; t0 += 64) {
        __syncthreads();
#pragma unroll
        for (int i = 0; i < 16; i++) {
            int v = threadIdx.x + i * 32;     // float4 index 0..511
            int tt = v >> 3;
            int p = (v & 7) << 2;
            *(float4*)&sBC[tt][p] = *(const float4*)(xdbl + (size_t)(t0 + tt) * 96 + 64 + p);
        }
        __syncthreads();
        if (fast) {
            for (int tt = 0; tt < 64; tt++) {
                int t = t0 + tt;
                float dl = delta[(size_t)t * DI + d];
                float u  = uc[(size_t)t * DI + d];
                float zz = xz[(size_t)t * (2*DI) + DI + d];
                float du = dl * u;
                float p1 = __expf(-dl);
                float p2 = p1*p1,  p3 = p2*p1,  p4 = p2*p2;
                float p5 = p3*p2,  p6 = p3*p3,  p7 = p4*p3,  p8 = p4*p4;
                float p9 = p5*p4,  p10 = p5*p5, p11 = p6*p5, p12 = p6*p6;
                float p13 = p7*p6, p14 = p7*p7, p15 = p8*p7, p16 = p8*p8;
                float e[16] = {p1,p2,p3,p4,p5,p6,p7,p8,p9,p10,p11,p12,p13,p14,p15,p16};
                float ac0 = 0.f, ac1 = 0.f, ac2 = 0.f, ac3 = 0.f;
#pragma unroll
                for (int n = 0; n < NSTATE; n += 4) {
                    h[n+0] = fmaf(e[n+0], h[n+0], du * sBC[tt][n+0]);
                    ac0 = fmaf(h[n+0], sBC[tt][16+n+0], ac0);
                    h[n+1] = fmaf(e[n+1], h[n+1], du * sBC[tt][n+1]);
                    ac1 = fmaf(h[n+1], sBC[tt][16+n+1], ac1);
                    h[n+2] = fmaf(e[n+2], h[n+2], du * sBC[tt][n+2]);
                    ac2 = fmaf(h[n+2], sBC[tt][16+n+2], ac2);
                    h[n+3] = fmaf(e[n+3], h[n+3], du * sBC[tt][n+3]);
                    ac3 = fmaf(h[n+3], sBC[tt][16+n+3], ac3);
                }
                float acc = (ac0 + ac1) + (ac2 + ac3);
                float y = fmaf(u, dsk, acc);
                float sg = zz / (1.f + __expf(-zz));
                yg[(size_t)t * DI + d] = y * sg;
            }
        } else {
            for (int tt = 0; tt < 64; tt++) {
                int t = t0 + tt;
                float dl = delta[(size_t)t * DI + d];
                float u  = uc[(size_t)t * DI + d];
                float zz = xz[(size_t)t * (2*DI) + DI + d];
                float du = dl * u;
                float ac0 = 0.f, ac1 = 0.f, ac2 = 0.f, ac3 = 0.f;
#pragma unroll
                for (int n = 0; n < NSTATE; n += 4) {
                    float e0 = __expf(dl * a[n+0]);
                    float e1 = __expf(dl * a[n+1]);
                    float e2 = __expf(dl * a[n+2]);
                    float e3 = __expf(dl * a[n+3]);
                    h[n+0] = fmaf(e0, h[n+0], du * sBC[tt][n+0]);
                    ac0 = fmaf(h[n+0], sBC[tt][16+n+0], ac0);
                    h[n+1] = fmaf(e1, h[n+1], du * sBC[tt][n+1]);
                    ac1 = fmaf(h[n+1], sBC[tt][16+n+1], ac1);
                    h[n+2] = fmaf(e2, h[n+2], du * sBC[tt][n+2]);
                    ac2 = fmaf(h[n+2], sBC[tt][16+n+2], ac2);
                    h[n+3] = fmaf(e3, h[n+3], du * sBC[tt][n+3]);
                    ac3 = fmaf(h[n+3], sBC[tt][16+n+3], ac3);
                }
                float acc = (ac0 + ac1) + (ac2 + ac3);
                float y = fmaf(u, dsk, acc);
                float sg = zz / (1.f + __expf(-zz));
                yg[(size_t)t * DI + d] = y * sg;
            }
        }
    }
}

// ------------------------------------------------------------------ launch --
extern "C" void kernel_launch(void* const* d_in, const int* in_sizes, int n_in,
                              void* d_out, int out_size)
{
    const float* x      = (const float*)d_in[0];
    const float* norm_w = (const float*)d_in[1];
    const float* in_w   = (const float*)d_in[2];
    const float* conv_w = (const float*)d_in[3];
    const float* conv_b = (const float*)d_in[4];
    const float* xproj_w= (const float*)d_in[5];
    const float* dt_w   = (const float*)d_in[6];
    const float* dt_b   = (const float*)d_in[7];
    const float* A_log  = (const float*)d_in[8];
    const float* D_skip = (const float*)d_in[9];
    const float* out_w  = (const float*)d_in[10];
    float* out = (float*)d_out;

    float *xn, *xz, *uc, *xdbl, *delta, *yg, *Amat;
    cudaGetSymbolAddress((void**)&xn,    g_xn);
    cudaGetSymbolAddress((void**)&xz,    g_xz);
    cudaGetSymbolAddress((void**)&uc,    g_uc);
    cudaGetSymbolAddress((void**)&xdbl,  g_xdbl);
    cudaGetSymbolAddress((void**)&delta, g_delta);
    cudaGetSymbolAddress((void**)&yg,    g_yg);
    cudaGetSymbolAddress((void**)&Amat,  g_A);

    // residual stream init: out = x
    cudaMemcpyAsync(out, x, (size_t)LSEQ * DMODEL * sizeof(float),
                    cudaMemcpyDeviceToDevice, 0);

    for (int lyr = 0; lyr < NL; lyr++) {
        const float* nw  = norm_w  + (size_t)lyr * DMODEL;
        const float* iw  = in_w    + (size_t)lyr * (2*DI) * DMODEL;
        const float* cw  = conv_w  + (size_t)lyr * DI * 4;
        const float* cb  = conv_b  + (size_t)lyr * DI;
        const float* xw  = xproj_w + (size_t)lyr * 96 * DI;
        const float* dw  = dt_w    + (size_t)lyr * DI * DTR;
        const float* db  = dt_b    + (size_t)lyr * DI;
        const float* al  = A_log   + (size_t)lyr * DI * NSTATE;
        const float* ds  = D_skip  + (size_t)lyr * DI;
        const float* ow  = out_w   + (size_t)lyr * DMODEL * DI;

        rmsnorm_kernel<<<LSEQ, 256>>>(out, nw, xn);
        sgemm128<false><<<dim3((2*DI)/128, LSEQ/128), 256>>>(xn, iw, xz, LSEQ, 2*DI, DMODEL);
        conv_silu_kernel<<<(LSEQ * DI) / 256, 256>>>(xz, cw, cb, uc);
        xproj_kernel<<<LSEQ / 32, 256>>>(uc, xw, xdbl);
        dt_kernel<<<dim3(DI/128, LSEQ/32), 256>>>(xdbl, dw, db, delta);
        set_flag_kernel<<<1, 1>>>();
        prepA_kernel<<<(DI * NSTATE) / 256, 256>>>(al);
        scan_kernel<<<DI / 32, 32>>>(delta, xdbl, uc, xz, Amat, ds, yg);
        sgemm128<true><<<dim3(DMODEL/128, LSEQ/128), 256>>>(yg, ow, out, LSEQ, DMODEL, DI);
    }
}